// round 12
// baseline (speedup 1.0000x reference)
#include <cuda_runtime.h>
#include <cuda_fp16.h>
#include <cstdint>

#define NN   100000
#define NE   1600000
#define NET  (NE + NN)      // edges + self loops
#define FF   256
#define HC   128
#define NH   4

// ---------------- scratch (device globals; no runtime allocation) ----------
__device__ __half g_hh[(size_t)NN * HC];    // projected features fp16 [N,128]
__device__ float g_asrc[NN * NH];           // per-node src attention half [N,4]
__device__ float g_adst[NN * NH];           // per-node dst attention half [N,4]
__device__ int   g_deg[NN];
__device__ int   g_off[NN + 1];
__device__ int   g_cur[NN];
__device__ int   g_srt[NET];                // src node id per CSR slot (by dst)
__device__ int   g_bs[128];                 // block sums for scan
__device__ __half g_wt[HC * FF];            // W^T fp16, K-major [n][k]

// ---------------- CSR build ------------------------------------------------
__global__ void k_init_deg() {
    int i = blockIdx.x * blockDim.x + threadIdx.x;
    if (i < NN) g_deg[i] = 1;               // self loop
}

__global__ void k_hist(const int* __restrict__ ei) {
    int e = blockIdx.x * blockDim.x + threadIdx.x;
    if (e < NE) atomicAdd(&g_deg[ei[NE + e]], 1);
}

__global__ void k_scan1() {
    __shared__ int sh[1024];
    int t = threadIdx.x;
    int i = blockIdx.x * 1024 + t;
    int v = (i < NN) ? g_deg[i] : 0;
    sh[t] = v;
    __syncthreads();
    #pragma unroll
    for (int off = 1; off < 1024; off <<= 1) {
        int x = sh[t];
        int y = (t >= off) ? sh[t - off] : 0;
        __syncthreads();
        sh[t] = x + y;
        __syncthreads();
    }
    int excl = (t == 0) ? 0 : sh[t - 1];
    if (i < NN) g_off[i] = excl;
    if (t == 1023) g_bs[blockIdx.x] = sh[1023];
}

__global__ void k_scan2() {                 // 1 block, 128 threads
    __shared__ int sh[128];
    int t = threadIdx.x;
    int v = (t < 98) ? g_bs[t] : 0;
    sh[t] = v;
    __syncthreads();
    #pragma unroll
    for (int off = 1; off < 128; off <<= 1) {
        int x = sh[t];
        int y = (t >= off) ? sh[t - off] : 0;
        __syncthreads();
        sh[t] = x + y;
        __syncthreads();
    }
    if (t < 98) g_bs[t] = sh[t] - v;        // exclusive
}

__global__ void k_scan3() {
    int i = blockIdx.x * blockDim.x + threadIdx.x;
    if (i < NN) {
        int o = g_off[i] + g_bs[i >> 10];
        g_off[i] = o;
        g_cur[i] = o;
        if (i == 0) g_off[NN] = NET;
    }
}

__global__ void k_fill(const int* __restrict__ ei) {
    int idx = blockIdx.x * blockDim.x + threadIdx.x;
    if (idx >= NET) return;
    int dst, src;
    if (idx < NE) { src = ei[idx]; dst = ei[NE + idx]; }
    else          { src = idx - NE; dst = idx - NE; }       // self loop
    int pos = atomicAdd(&g_cur[dst], 1);
    g_srt[pos] = src;
}

// ---------------- W prep: transpose to fp16 K-major -------------------------
__global__ void k_prepw(const float* __restrict__ W) {
    int idx = blockIdx.x * blockDim.x + threadIdx.x;
    if (idx >= HC * FF) return;
    int n = idx >> 8, k = idx & 255;
    g_wt[idx] = __float2half(W[k * HC + n]);
}

// ---------------- GEMM: single-term fp16 mma.sync ----------------------------
// CTA tile M=128, N=128, K staged in chunks of 64.
// 8 warps = 4(m) x 2(n); warp tile 32x64 (two heads of 32 cols).

#define LDA 72                 // padded row stride in halves (144B: conflict-free)

__device__ __forceinline__ uint32_t smem_u32(const void* p) {
    uint32_t a;
    asm("{ .reg .u64 t; cvta.to.shared.u64 t, %1; cvt.u32.u64 %0, t; }"
        : "=r"(a) : "l"(p));
    return a;
}

__device__ __forceinline__ void ldm_x4(uint32_t* r, uint32_t addr) {
    asm volatile("ldmatrix.sync.aligned.m8n8.x4.shared.b16 {%0,%1,%2,%3}, [%4];"
                 : "=r"(r[0]), "=r"(r[1]), "=r"(r[2]), "=r"(r[3]) : "r"(addr));
}

__device__ __forceinline__ void mma_f16(float* d, const uint32_t* a, const uint32_t* b) {
    asm volatile(
        "mma.sync.aligned.m16n8k16.row.col.f32.f16.f16.f32 "
        "{%0,%1,%2,%3}, {%4,%5,%6,%7}, {%8,%9}, {%0,%1,%2,%3};"
        : "+f"(d[0]), "+f"(d[1]), "+f"(d[2]), "+f"(d[3])
        : "r"(a[0]), "r"(a[1]), "r"(a[2]), "r"(a[3]), "r"(b[0]), "r"(b[1]));
}

__global__ void __launch_bounds__(256, 2) k_gemm(
    const float* __restrict__ x,
    const float* __restrict__ att_s, const float* __restrict__ att_d)
{
    __shared__ float sAs[HC], sAd[HC];
    __shared__ float sa[128 * NH], sd[128 * NH];
    __shared__ __half sA[128 * LDA];
    __shared__ __half sB[128 * LDA];

    int tid = threadIdx.x;
    int wid = tid >> 5, lane = tid & 31;
    int wm = wid >> 1, wn = wid & 1;       // warp grid 4x2
    int row0 = blockIdx.x * 128;

    if (tid < HC) { sAs[tid] = att_s[tid]; sAd[tid] = att_d[tid]; }
    for (int q = tid; q < 128 * NH; q += 256) { sa[q] = 0.f; sd[q] = 0.f; }

    float acc[2][8][4];
    #pragma unroll
    for (int tm = 0; tm < 2; tm++)
        #pragma unroll
        for (int tn = 0; tn < 8; tn++)
            #pragma unroll
            for (int q = 0; q < 4; q++) acc[tm][tn][q] = 0.f;

    uint32_t a_base = smem_u32(sA);
    uint32_t b_base = smem_u32(sB);
    uint32_t a_row = (uint32_t)(wm * 32 + (lane & 15));
    uint32_t a_kh  = (uint32_t)((lane >> 4) << 3);
    uint32_t b_row = (uint32_t)(wn * 64 + (lane & 7) + ((lane >> 4) << 3));
    uint32_t b_kh  = (uint32_t)(((lane >> 3) & 1) << 3);

    for (int kc = 0; kc < FF; kc += 64) {
        // ---- stage A: x[row0..row0+127][kc..kc+63] -> fp16 ----
        #pragma unroll
        for (int it = 0; it < 8; it++) {
            int i = tid + it * 256;
            int r = i >> 4, g = i & 15;
            float4 v = make_float4(0.f, 0.f, 0.f, 0.f);
            int grow = row0 + r;
            if (grow < NN)
                v = *(const float4*)&x[(size_t)grow * FF + kc + g * 4];
            *(__half2*)&sA[r * LDA + g * 4]     = __floats2half2_rn(v.x, v.y);
            *(__half2*)&sA[r * LDA + g * 4 + 2] = __floats2half2_rn(v.z, v.w);
        }
        // ---- stage B: W^T[n][kc..kc+63] fp16 ----
        #pragma unroll
        for (int it = 0; it < 4; it++) {
            int i = tid + it * 256;
            int n = i >> 3, g = i & 7;
            uint4 hv = *(const uint4*)&g_wt[n * FF + kc + g * 8];
            *(uint4*)&sB[n * LDA + g * 8] = hv;
        }
        __syncthreads();

        #pragma unroll
        for (int kk = 0; kk < 4; kk++) {
            uint32_t akb = (uint32_t)(kk * 16);
            uint32_t ah[2][4], bh[8][2];
            #pragma unroll
            for (int tm = 0; tm < 2; tm++) {
                uint32_t off = ((a_row + tm * 16) * LDA + akb + a_kh) * 2;
                ldm_x4(ah[tm], a_base + off);
            }
            #pragma unroll
            for (int pr = 0; pr < 4; pr++) {
                uint32_t off = ((b_row + pr * 16) * LDA + akb + b_kh) * 2;
                uint32_t t4[4];
                ldm_x4(t4, b_base + off);
                bh[pr * 2][0] = t4[0]; bh[pr * 2][1] = t4[1];
                bh[pr * 2 + 1][0] = t4[2]; bh[pr * 2 + 1][1] = t4[3];
            }
            #pragma unroll
            for (int tm = 0; tm < 2; tm++)
                #pragma unroll
                for (int tn = 0; tn < 8; tn++)
                    mma_f16(acc[tm][tn], ah[tm], bh[tn]);
        }
        __syncthreads();
    }

    // ---- epilogue: write h (fp16), fused attention halves ----
    int qr = lane >> 2, qc = lane & 3;
    int h0 = wn * 2, h1 = wn * 2 + 1;
    #pragma unroll
    for (int tm = 0; tm < 2; tm++) {
        #pragma unroll
        for (int half = 0; half < 2; half++) {
            int r = wm * 32 + tm * 16 + half * 8 + qr;
            int grow = row0 + r;
            float ps0 = 0.f, pd0 = 0.f, ps1 = 0.f, pd1 = 0.f;
            #pragma unroll
            for (int tn = 0; tn < 8; tn++) {
                float c0 = acc[tm][tn][half * 2];
                float c1 = acc[tm][tn][half * 2 + 1];
                int col = wn * 64 + tn * 8 + qc * 2;
                if (tn < 4) {
                    ps0 = fmaf(c0, sAs[col], fmaf(c1, sAs[col + 1], ps0));
                    pd0 = fmaf(c0, sAd[col], fmaf(c1, sAd[col + 1], pd0));
                } else {
                    ps1 = fmaf(c0, sAs[col], fmaf(c1, sAs[col + 1], ps1));
                    pd1 = fmaf(c0, sAd[col], fmaf(c1, sAd[col + 1], pd1));
                }
                if (grow < NN)
                    *(__half2*)&g_hh[(size_t)grow * HC + col] = __floats2half2_rn(c0, c1);
            }
            atomicAdd(&sa[r * NH + h0], ps0);
            atomicAdd(&sd[r * NH + h0], pd0);
            atomicAdd(&sa[r * NH + h1], ps1);
            atomicAdd(&sd[r * NH + h1], pd1);
        }
    }
    __syncthreads();
    for (int q = tid; q < 128 * NH; q += 256) {
        int r = q >> 2, hh = q & 3;
        int grow = row0 + r;
        if (grow < NN) {
            g_asrc[grow * NH + hh] = sa[r * NH + hh];
            g_adst[grow * NH + hh] = sd[r * NH + hh];
        }
    }
}

// ---------------- single-pass softmax-aggregate (warp per node) -------------
// out = (sum_e p_e * h_src(e)) / (sum_e p_e); p_e = exp(lrelu(logit)).
// Chunk stage computes 32 edges' exps vectorially into per-warp smem;
// inner loop is LDS+LDS+LDG.64+FMA only (no SHFL / MUFU / scalar LDG).
__device__ __forceinline__ float lrelu(float v) { return v > 0.f ? v : 0.2f * v; }

__global__ void __launch_bounds__(256) k_gat(
    const float* __restrict__ bias, float* __restrict__ out)
{
    __shared__ int   sj[8][32];
    __shared__ float sp[8][NH * 33];       // pad 33: head*33+t hits distinct banks

    int wip = threadIdx.x >> 5;
    int w = (blockIdx.x * blockDim.x + threadIdx.x) >> 5;
    int lane = threadIdx.x & 31;
    if (w >= NN) return;

    int o0 = g_off[w];
    int d = g_off[w + 1] - o0;
    int head = lane >> 3;                  // lane owns channels lane*4..lane*4+3
    float4 adst = *(const float4*)&g_adst[w * NH];
    int*   mj = sj[wip];
    float* mp = sp[wip];

    float psum = 0.f;
    float4 acc = make_float4(0.f, 0.f, 0.f, 0.f);
    for (int base = 0; base < d; base += 32) {
        int idx = base + lane;
        if (idx < d) {
            int j = g_srt[o0 + idx];
            float4 as = *(const float4*)&g_asrc[j * NH];
            mj[lane] = j;
            mp[0 * 33 + lane] = __expf(lrelu(as.x + adst.x));
            mp[1 * 33 + lane] = __expf(lrelu(as.y + adst.y));
            mp[2 * 33 + lane] = __expf(lrelu(as.z + adst.z));
            mp[3 * 33 + lane] = __expf(lrelu(as.w + adst.w));
        }
        __syncwarp();
        int cnt = min(32, d - base);
        #pragma unroll 4
        for (int t = 0; t < cnt; t++) {
            int j = mj[t];                         // broadcast LDS
            float p = mp[head * 33 + t];           // 4 banks, 8-lane broadcast
            psum += p;
            uint2 u = *(const uint2*)&g_hh[(size_t)j * HC + lane * 4];
            float2 f0 = __half22float2(*(__half2*)&u.x);
            float2 f1 = __half22float2(*(__half2*)&u.y);
            acc.x = fmaf(p, f0.x, acc.x);
            acc.y = fmaf(p, f0.y, acc.y);
            acc.z = fmaf(p, f1.x, acc.z);
            acc.w = fmaf(p, f1.y, acc.w);
        }
        __syncwarp();
    }
    float ih = 1.f / (psum + 1e-16f);
    float4 b = *(const float4*)&bias[lane * 4];
    float4 o = make_float4(fmaf(acc.x, ih, b.x), fmaf(acc.y, ih, b.y),
                           fmaf(acc.z, ih, b.z), fmaf(acc.w, ih, b.w));
    *(float4*)&out[(size_t)w * HC + lane * 4] = o;
}

// ---------------- launch ----------------------------------------------------
extern "C" void kernel_launch(void* const* d_in, const int* in_sizes, int n_in,
                              void* d_out, int out_size)
{
    const float* x     = (const float*)d_in[0];
    const int*   ei    = (const int*)d_in[1];
    const float* W     = (const float*)d_in[2];
    const float* att_s = (const float*)d_in[3];
    const float* att_d = (const float*)d_in[4];
    const float* bias  = (const float*)d_in[5];
    float* out = (float*)d_out;

    const int NB = (NN + 1023) / 1024;   // 98

    static cudaStream_t s2 = nullptr;
    static cudaEvent_t evA = nullptr, evB = nullptr;
    if (s2 == nullptr) {
        cudaStreamCreate(&s2);
        cudaEventCreateWithFlags(&evA, cudaEventDisableTiming);
        cudaEventCreateWithFlags(&evB, cudaEventDisableTiming);
    }

    // fork: CSR build on side stream, concurrent with W-prep + GEMM
    cudaEventRecord(evA, 0);
    cudaStreamWaitEvent(s2, evA, 0);

    k_init_deg<<<(NN + 255) / 256, 256, 0, s2>>>();
    k_hist<<<(NE + 255) / 256, 256, 0, s2>>>(ei);
    k_scan1<<<NB, 1024, 0, s2>>>();
    k_scan2<<<1, 128, 0, s2>>>();
    k_scan3<<<(NN + 255) / 256, 256, 0, s2>>>();
    k_fill<<<(NET + 255) / 256, 256, 0, s2>>>(ei);
    cudaEventRecord(evB, s2);

    k_prepw<<<(HC * FF + 255) / 256, 256>>>(W);
    k_gemm<<<(NN + 127) / 128, 256>>>(x, att_s, att_d);

    // join: k_gat needs both CSR and GEMM results
    cudaStreamWaitEvent(0, evB, 0);
    k_gat<<<(NN * 32 + 255) / 256, 256>>>(bias, out);
}

// round 13
// speedup vs baseline: 1.0220x; 1.0220x over previous
#include <cuda_runtime.h>
#include <cuda_fp16.h>
#include <cstdint>

#define NN   100000
#define NE   1600000
#define NET  (NE + NN)      // edges + self loops
#define FF   256
#define HC   128
#define NH   4

// ---------------- scratch (device globals; no runtime allocation) ----------
__device__ __half g_hh[(size_t)NN * HC];    // projected features fp16 [N,128]
__device__ float g_asrc[NN * NH];           // per-node src attention half [N,4]
__device__ float g_adst[NN * NH];           // per-node dst attention half [N,4]
__device__ int   g_deg[NN];                 // zero at entry; re-zeroed by k_scan1
__device__ int   g_off[NN + 1];
__device__ int   g_cur[NN];
__device__ int   g_srt[NET];                // src node id per CSR slot (by dst)
__device__ int   g_bs[128];                 // block sums for scan
__device__ __half g_wt[HC * FF];            // W^T fp16, K-major [n][k]

// ---------------- CSR build ------------------------------------------------
__global__ void k_hist(const int* __restrict__ ei) {
    int e = blockIdx.x * blockDim.x + threadIdx.x;
    if (e < NE) atomicAdd(&g_deg[ei[NE + e]], 1);
}

__global__ void k_scan1() {
    __shared__ int sh[1024];
    int t = threadIdx.x;
    int i = blockIdx.x * 1024 + t;
    int v = 0;
    if (i < NN) {
        v = g_deg[i] + 1;           // +1 = self loop (init_deg fused)
        g_deg[i] = 0;               // reset for next graph replay
    }
    sh[t] = v;
    __syncthreads();
    #pragma unroll
    for (int off = 1; off < 1024; off <<= 1) {
        int x = sh[t];
        int y = (t >= off) ? sh[t - off] : 0;
        __syncthreads();
        sh[t] = x + y;
        __syncthreads();
    }
    int excl = (t == 0) ? 0 : sh[t - 1];
    if (i < NN) g_off[i] = excl;
    if (t == 1023) g_bs[blockIdx.x] = sh[1023];
}

__global__ void k_scan2() {                 // 1 block, 128 threads
    __shared__ int sh[128];
    int t = threadIdx.x;
    int v = (t < 98) ? g_bs[t] : 0;
    sh[t] = v;
    __syncthreads();
    #pragma unroll
    for (int off = 1; off < 128; off <<= 1) {
        int x = sh[t];
        int y = (t >= off) ? sh[t - off] : 0;
        __syncthreads();
        sh[t] = x + y;
        __syncthreads();
    }
    if (t < 98) g_bs[t] = sh[t] - v;        // exclusive
}

__global__ void k_scan3() {
    int i = blockIdx.x * blockDim.x + threadIdx.x;
    if (i < NN) {
        int o = g_off[i] + g_bs[i >> 10];
        g_off[i] = o;
        g_cur[i] = o;
        if (i == 0) g_off[NN] = NET;
    }
}

__global__ void k_fill(const int* __restrict__ ei) {
    int idx = blockIdx.x * blockDim.x + threadIdx.x;
    if (idx >= NET) return;
    int dst, src;
    if (idx < NE) { src = ei[idx]; dst = ei[NE + idx]; }
    else          { src = idx - NE; dst = idx - NE; }       // self loop
    int pos = atomicAdd(&g_cur[dst], 1);
    g_srt[pos] = src;
}

// ---------------- W prep: transpose to fp16 K-major -------------------------
__global__ void k_prepw(const float* __restrict__ W) {
    int idx = blockIdx.x * blockDim.x + threadIdx.x;
    if (idx >= HC * FF) return;
    int n = idx >> 8, k = idx & 255;
    g_wt[idx] = __float2half(W[k * HC + n]);
}

// ---------------- GEMM: single-term fp16 mma.sync ----------------------------
// CTA tile M=64, N=128, K staged in chunks of 64.
// 8 warps = 2(m) x 4(n); warp tile 32x32 (one head of 32 cols).

#define LDA 72                 // padded row stride in halves (144B: conflict-free)

__device__ __forceinline__ uint32_t smem_u32(const void* p) {
    uint32_t a;
    asm("{ .reg .u64 t; cvta.to.shared.u64 t, %1; cvt.u32.u64 %0, t; }"
        : "=r"(a) : "l"(p));
    return a;
}

__device__ __forceinline__ void ldm_x4(uint32_t* r, uint32_t addr) {
    asm volatile("ldmatrix.sync.aligned.m8n8.x4.shared.b16 {%0,%1,%2,%3}, [%4];"
                 : "=r"(r[0]), "=r"(r[1]), "=r"(r[2]), "=r"(r[3]) : "r"(addr));
}

__device__ __forceinline__ void mma_f16(float* d, const uint32_t* a, const uint32_t* b) {
    asm volatile(
        "mma.sync.aligned.m16n8k16.row.col.f32.f16.f16.f32 "
        "{%0,%1,%2,%3}, {%4,%5,%6,%7}, {%8,%9}, {%0,%1,%2,%3};"
        : "+f"(d[0]), "+f"(d[1]), "+f"(d[2]), "+f"(d[3])
        : "r"(a[0]), "r"(a[1]), "r"(a[2]), "r"(a[3]), "r"(b[0]), "r"(b[1]));
}

__global__ void __launch_bounds__(256, 2) k_gemm(
    const float* __restrict__ x,
    const float* __restrict__ att_s, const float* __restrict__ att_d)
{
    __shared__ float sAs[HC], sAd[HC];
    __shared__ float sa[64 * NH], sd[64 * NH];
    __shared__ __half sA[64 * LDA];
    __shared__ __half sB[128 * LDA];

    int tid = threadIdx.x;
    int wid = tid >> 5, lane = tid & 31;
    int wm = wid >> 2, wn = wid & 3;       // warp grid 2x4
    int row0 = blockIdx.x * 64;

    if (tid < HC) { sAs[tid] = att_s[tid]; sAd[tid] = att_d[tid]; }
    if (tid < 256) { sa[tid] = 0.f; sd[tid] = 0.f; }

    float acc[2][4][4];
    #pragma unroll
    for (int tm = 0; tm < 2; tm++)
        #pragma unroll
        for (int tn = 0; tn < 4; tn++)
            #pragma unroll
            for (int q = 0; q < 4; q++) acc[tm][tn][q] = 0.f;

    uint32_t a_base = smem_u32(sA);
    uint32_t b_base = smem_u32(sB);
    uint32_t a_row = (uint32_t)(wm * 32 + (lane & 15));
    uint32_t a_kh  = (uint32_t)((lane >> 4) << 3);
    uint32_t b_row = (uint32_t)(wn * 32 + (lane & 7) + ((lane >> 4) << 3));
    uint32_t b_kh  = (uint32_t)(((lane >> 3) & 1) << 3);

    for (int kc = 0; kc < FF; kc += 64) {
        // ---- stage A: x[row0..row0+63][kc..kc+63] -> fp16 ----
        #pragma unroll
        for (int it = 0; it < 4; it++) {
            int i = tid + it * 256;
            int r = i >> 4, g = i & 15;
            float4 v = make_float4(0.f, 0.f, 0.f, 0.f);
            int grow = row0 + r;
            if (grow < NN)
                v = *(const float4*)&x[(size_t)grow * FF + kc + g * 4];
            __half2 h0 = __floats2half2_rn(v.x, v.y);
            __half2 h1 = __floats2half2_rn(v.z, v.w);
            *(__half2*)&sA[r * LDA + g * 4]     = h0;
            *(__half2*)&sA[r * LDA + g * 4 + 2] = h1;
        }
        // ---- stage B: W^T[n][kc..kc+63] fp16 ----
        #pragma unroll
        for (int it = 0; it < 4; it++) {
            int i = tid + it * 256;
            int n = i >> 3, g = i & 7;
            uint4 hv = *(const uint4*)&g_wt[n * FF + kc + g * 8];
            *(uint4*)&sB[n * LDA + g * 8] = hv;
        }
        __syncthreads();

        #pragma unroll
        for (int kk = 0; kk < 4; kk++) {
            uint32_t akb = (uint32_t)(kk * 16);
            uint32_t ah[2][4], bh[4][2];
            #pragma unroll
            for (int tm = 0; tm < 2; tm++) {
                uint32_t off = ((a_row + tm * 16) * LDA + akb + a_kh) * 2;
                ldm_x4(ah[tm], a_base + off);
            }
            #pragma unroll
            for (int pr = 0; pr < 2; pr++) {
                uint32_t off = ((b_row + pr * 16) * LDA + akb + b_kh) * 2;
                uint32_t t4[4];
                ldm_x4(t4, b_base + off);
                bh[pr * 2][0] = t4[0]; bh[pr * 2][1] = t4[1];
                bh[pr * 2 + 1][0] = t4[2]; bh[pr * 2 + 1][1] = t4[3];
            }
            #pragma unroll
            for (int tm = 0; tm < 2; tm++)
                #pragma unroll
                for (int tn = 0; tn < 4; tn++)
                    mma_f16(acc[tm][tn], ah[tm], bh[tn]);
        }
        __syncthreads();
    }

    // ---- epilogue: write h (fp16), fused attention halves ----
    int qr = lane >> 2, qc = lane & 3;
    #pragma unroll
    for (int tm = 0; tm < 2; tm++) {
        #pragma unroll
        for (int half = 0; half < 2; half++) {
            int r = wm * 32 + tm * 16 + half * 8 + qr;
            int grow = row0 + r;
            float ps = 0.f, pd = 0.f;
            #pragma unroll
            for (int tn = 0; tn < 4; tn++) {
                float c0 = acc[tm][tn][half * 2];
                float c1 = acc[tm][tn][half * 2 + 1];
                int col = wn * 32 + tn * 8 + qc * 2;
                ps = fmaf(c0, sAs[col], fmaf(c1, sAs[col + 1], ps));
                pd = fmaf(c0, sAd[col], fmaf(c1, sAd[col + 1], pd));
                if (grow < NN)
                    *(__half2*)&g_hh[(size_t)grow * HC + col] = __floats2half2_rn(c0, c1);
            }
            atomicAdd(&sa[r * NH + wn], ps);
            atomicAdd(&sd[r * NH + wn], pd);
        }
    }
    __syncthreads();
    if (tid < 256) {
        int r = tid >> 2, hh = tid & 3;
        int grow = row0 + r;
        if (grow < NN) {
            g_asrc[grow * NH + hh] = sa[r * NH + hh];
            g_adst[grow * NH + hh] = sd[r * NH + hh];
        }
    }
}

// ---------------- single-pass softmax-aggregate (warp per node) -------------
// out = (sum_e p_e * h_src(e)) / (sum_e p_e); p_e = exp(lrelu(logit)).
// Chunk stage computes 32 edges' exps vectorially into per-warp smem;
// inner loop is LDS+LDS+LDG.64+FMA only (no SHFL / MUFU / scalar LDG).
__device__ __forceinline__ float lrelu(float v) { return v > 0.f ? v : 0.2f * v; }

__global__ void __launch_bounds__(256) k_gat(
    const float* __restrict__ bias, float* __restrict__ out)
{
    __shared__ int   sj[8][32];
    __shared__ float sp[8][NH * 33];       // pad 33: head*33+t hits distinct banks

    int wip = threadIdx.x >> 5;
    int w = (blockIdx.x * blockDim.x + threadIdx.x) >> 5;
    int lane = threadIdx.x & 31;
    if (w >= NN) return;

    int o0 = g_off[w];
    int d = g_off[w + 1] - o0;
    int head = lane >> 3;                  // lane owns channels lane*4..lane*4+3
    float4 adst = *(const float4*)&g_adst[w * NH];
    int*   mj = sj[wip];
    float* mp = sp[wip];

    float psum = 0.f;
    float4 acc = make_float4(0.f, 0.f, 0.f, 0.f);
    for (int base = 0; base < d; base += 32) {
        int idx = base + lane;
        if (idx < d) {
            int j = g_srt[o0 + idx];
            float4 as = *(const float4*)&g_asrc[j * NH];
            mj[lane] = j;
            mp[0 * 33 + lane] = __expf(lrelu(as.x + adst.x));
            mp[1 * 33 + lane] = __expf(lrelu(as.y + adst.y));
            mp[2 * 33 + lane] = __expf(lrelu(as.z + adst.z));
            mp[3 * 33 + lane] = __expf(lrelu(as.w + adst.w));
        }
        __syncwarp();
        int cnt = min(32, d - base);
        for (int t = 0; t < cnt; t++) {
            int j = mj[t];                         // broadcast LDS
            float p = mp[head * 33 + t];           // 4 banks, 8-lane broadcast
            psum += p;
            uint2 u = *(const uint2*)&g_hh[(size_t)j * HC + lane * 4];
            float2 f0 = __half22float2(*(__half2*)&u.x);
            float2 f1 = __half22float2(*(__half2*)&u.y);
            acc.x = fmaf(p, f0.x, acc.x);
            acc.y = fmaf(p, f0.y, acc.y);
            acc.z = fmaf(p, f1.x, acc.z);
            acc.w = fmaf(p, f1.y, acc.w);
        }
        __syncwarp();
    }
    float ih = 1.f / (psum + 1e-16f);
    float4 b = *(const float4*)&bias[lane * 4];
    float4 o = make_float4(fmaf(acc.x, ih, b.x), fmaf(acc.y, ih, b.y),
                           fmaf(acc.z, ih, b.z), fmaf(acc.w, ih, b.w));
    *(float4*)&out[(size_t)w * HC + lane * 4] = o;
}

// ---------------- launch ----------------------------------------------------
extern "C" void kernel_launch(void* const* d_in, const int* in_sizes, int n_in,
                              void* d_out, int out_size)
{
    const float* x     = (const float*)d_in[0];
    const int*   ei    = (const int*)d_in[1];
    const float* W     = (const float*)d_in[2];
    const float* att_s = (const float*)d_in[3];
    const float* att_d = (const float*)d_in[4];
    const float* bias  = (const float*)d_in[5];
    float* out = (float*)d_out;

    const int NB = (NN + 1023) / 1024;   // 98

    static cudaStream_t s2 = nullptr;
    static cudaEvent_t evA = nullptr, evB = nullptr;
    if (s2 == nullptr) {
        cudaStreamCreate(&s2);
        cudaEventCreateWithFlags(&evA, cudaEventDisableTiming);
        cudaEventCreateWithFlags(&evB, cudaEventDisableTiming);
    }

    // fork: CSR build on side stream, concurrent with W-prep + GEMM
    cudaEventRecord(evA, 0);
    cudaStreamWaitEvent(s2, evA, 0);

    k_hist<<<(NE + 255) / 256, 256, 0, s2>>>(ei);
    k_scan1<<<NB, 1024, 0, s2>>>();
    k_scan2<<<1, 128, 0, s2>>>();
    k_scan3<<<(NN + 255) / 256, 256, 0, s2>>>();
    k_fill<<<(NET + 255) / 256, 256, 0, s2>>>(ei);
    cudaEventRecord(evB, s2);

    k_prepw<<<(HC * FF + 255) / 256, 256>>>(W);
    k_gemm<<<(NN + 63) / 64, 256>>>(x, att_s, att_d);

    // join: k_gat needs both CSR and GEMM results
    cudaStreamWaitEvent(0, evB, 0);
    k_gat<<<(NN * 32 + 255) / 256, 256>>>(bias, out);
}

// round 14
// speedup vs baseline: 1.0622x; 1.0393x over previous
#include <cuda_runtime.h>
#include <cuda_fp16.h>
#include <cstdint>

#define NN   100000
#define NE   1600000
#define NET  (NE + NN)      // edges + self loops
#define FF   256
#define HC   128
#define NH   4

// ---------------- scratch (device globals; no runtime allocation) ----------
__device__ __half g_hh[(size_t)NN * HC];    // projected features fp16 [N,128]
__device__ float g_asrc[NN * NH];           // per-node src attention half [N,4]
__device__ float g_adst[NN * NH];           // per-node dst attention half [N,4]
__device__ int   g_deg[NN];                 // zero at entry; re-zeroed by k_scan1
__device__ int   g_off[NN + 1];
__device__ int   g_cur[NN];
__device__ int   g_srt[NET];                // src node id per CSR slot (by dst)
__device__ int   g_bs[128];                 // block sums for scan
__device__ __half g_wt[HC * FF];            // W^T fp16, K-major [n][k]

// ---------------- CSR build ------------------------------------------------
__global__ void k_hist(const int* __restrict__ ei) {
    int e = blockIdx.x * blockDim.x + threadIdx.x;
    if (e < NE) atomicAdd(&g_deg[ei[NE + e]], 1);
}

__global__ void k_scan1() {
    __shared__ int sh[1024];
    int t = threadIdx.x;
    int i = blockIdx.x * 1024 + t;
    int v = 0;
    if (i < NN) {
        v = g_deg[i] + 1;           // +1 = self loop (init_deg fused)
        g_deg[i] = 0;               // reset for next graph replay
    }
    sh[t] = v;
    __syncthreads();
    #pragma unroll
    for (int off = 1; off < 1024; off <<= 1) {
        int x = sh[t];
        int y = (t >= off) ? sh[t - off] : 0;
        __syncthreads();
        sh[t] = x + y;
        __syncthreads();
    }
    int excl = (t == 0) ? 0 : sh[t - 1];
    if (i < NN) g_off[i] = excl;
    if (t == 1023) g_bs[blockIdx.x] = sh[1023];
}

__global__ void k_scan2() {                 // 1 block, 128 threads
    __shared__ int sh[128];
    int t = threadIdx.x;
    int v = (t < 98) ? g_bs[t] : 0;
    sh[t] = v;
    __syncthreads();
    #pragma unroll
    for (int off = 1; off < 128; off <<= 1) {
        int x = sh[t];
        int y = (t >= off) ? sh[t - off] : 0;
        __syncthreads();
        sh[t] = x + y;
        __syncthreads();
    }
    if (t < 98) g_bs[t] = sh[t] - v;        // exclusive
}

__global__ void k_scan3() {
    int i = blockIdx.x * blockDim.x + threadIdx.x;
    if (i < NN) {
        int o = g_off[i] + g_bs[i >> 10];
        g_off[i] = o;
        g_cur[i] = o;
        if (i == 0) g_off[NN] = NET;
    }
}

__global__ void k_fill(const int* __restrict__ ei) {
    int idx = blockIdx.x * blockDim.x + threadIdx.x;
    if (idx >= NET) return;
    int dst, src;
    if (idx < NE) { src = ei[idx]; dst = ei[NE + idx]; }
    else          { src = idx - NE; dst = idx - NE; }       // self loop
    int pos = atomicAdd(&g_cur[dst], 1);
    g_srt[pos] = src;
}

// ---------------- W prep: transpose to fp16 K-major -------------------------
__global__ void k_prepw(const float* __restrict__ W) {
    int idx = blockIdx.x * blockDim.x + threadIdx.x;
    if (idx >= HC * FF) return;
    int n = idx >> 8, k = idx & 255;
    g_wt[idx] = __float2half(W[k * HC + n]);
}

// ---------------- GEMM: single-term fp16 mma.sync, double-buffered ----------
// CTA tile M=64, N=128, K staged in chunks of 64; next chunk's global loads
// are prefetched into registers while the current chunk runs mma.
// 8 warps = 2(m) x 4(n); warp tile 32x32 (one head of 32 cols).

#define LDA 72                 // padded row stride in halves (144B: conflict-free)

__device__ __forceinline__ uint32_t smem_u32(const void* p) {
    uint32_t a;
    asm("{ .reg .u64 t; cvta.to.shared.u64 t, %1; cvt.u32.u64 %0, t; }"
        : "=r"(a) : "l"(p));
    return a;
}

__device__ __forceinline__ void ldm_x4(uint32_t* r, uint32_t addr) {
    asm volatile("ldmatrix.sync.aligned.m8n8.x4.shared.b16 {%0,%1,%2,%3}, [%4];"
                 : "=r"(r[0]), "=r"(r[1]), "=r"(r[2]), "=r"(r[3]) : "r"(addr));
}

__device__ __forceinline__ void mma_f16(float* d, const uint32_t* a, const uint32_t* b) {
    asm volatile(
        "mma.sync.aligned.m16n8k16.row.col.f32.f16.f16.f32 "
        "{%0,%1,%2,%3}, {%4,%5,%6,%7}, {%8,%9}, {%0,%1,%2,%3};"
        : "+f"(d[0]), "+f"(d[1]), "+f"(d[2]), "+f"(d[3])
        : "r"(a[0]), "r"(a[1]), "r"(a[2]), "r"(a[3]), "r"(b[0]), "r"(b[1]));
}

__global__ void __launch_bounds__(256, 2) k_gemm(
    const float* __restrict__ x,
    const float* __restrict__ att_s, const float* __restrict__ att_d)
{
    __shared__ float sAs[HC], sAd[HC];
    __shared__ float sa[64 * NH], sd[64 * NH];
    __shared__ __half sA[64 * LDA];
    __shared__ __half sB[128 * LDA];

    int tid = threadIdx.x;
    int wid = tid >> 5, lane = tid & 31;
    int wm = wid >> 2, wn = wid & 3;       // warp grid 2x4
    int row0 = blockIdx.x * 64;

    if (tid < HC) { sAs[tid] = att_s[tid]; sAd[tid] = att_d[tid]; }
    if (tid < 256) { sa[tid] = 0.f; sd[tid] = 0.f; }

    float acc[2][4][4];
    #pragma unroll
    for (int tm = 0; tm < 2; tm++)
        #pragma unroll
        for (int tn = 0; tn < 4; tn++)
            #pragma unroll
            for (int q = 0; q < 4; q++) acc[tm][tn][q] = 0.f;

    uint32_t a_base = smem_u32(sA);
    uint32_t b_base = smem_u32(sB);
    uint32_t a_row = (uint32_t)(wm * 32 + (lane & 15));
    uint32_t a_kh  = (uint32_t)((lane >> 4) << 3);
    uint32_t b_row = (uint32_t)(wn * 32 + (lane & 7) + ((lane >> 4) << 3));
    uint32_t b_kh  = (uint32_t)(((lane >> 3) & 1) << 3);

    // per-thread staging indices (constant across chunks)
    int ar = tid >> 4, ag = tid & 15;      // A: row, float4-group (+64 rows per it? no: it adds 256 threads -> +16 rows)
    int bn = tid >> 3, bg = tid & 7;       // B: n, uint4-group

    float4 pa[4];
    uint4  pb[4];

    // ---- prefetch chunk 0 ----
    #pragma unroll
    for (int it = 0; it < 4; it++) {
        int r = ar + it * 16;
        int grow = row0 + r;
        pa[it] = (grow < NN) ? *(const float4*)&x[(size_t)grow * FF + ag * 4]
                             : make_float4(0.f, 0.f, 0.f, 0.f);
        int n = bn + it * 32;
        pb[it] = *(const uint4*)&g_wt[n * FF + bg * 8];
    }

    for (int kc = 0; kc < FF; kc += 64) {
        // ---- store prefetched chunk into smem ----
        #pragma unroll
        for (int it = 0; it < 4; it++) {
            int r = ar + it * 16;
            *(__half2*)&sA[r * LDA + ag * 4]     = __floats2half2_rn(pa[it].x, pa[it].y);
            *(__half2*)&sA[r * LDA + ag * 4 + 2] = __floats2half2_rn(pa[it].z, pa[it].w);
            int n = bn + it * 32;
            *(uint4*)&sB[n * LDA + bg * 8] = pb[it];
        }
        __syncthreads();

        // ---- prefetch next chunk (overlaps with mma below) ----
        if (kc + 64 < FF) {
            #pragma unroll
            for (int it = 0; it < 4; it++) {
                int r = ar + it * 16;
                int grow = row0 + r;
                pa[it] = (grow < NN)
                    ? *(const float4*)&x[(size_t)grow * FF + kc + 64 + ag * 4]
                    : make_float4(0.f, 0.f, 0.f, 0.f);
                int n = bn + it * 32;
                pb[it] = *(const uint4*)&g_wt[n * FF + kc + 64 + bg * 8];
            }
        }

        #pragma unroll
        for (int kk = 0; kk < 4; kk++) {
            uint32_t akb = (uint32_t)(kk * 16);
            uint32_t ah[2][4], bh[4][2];
            #pragma unroll
            for (int tm = 0; tm < 2; tm++) {
                uint32_t off = ((a_row + tm * 16) * LDA + akb + a_kh) * 2;
                ldm_x4(ah[tm], a_base + off);
            }
            #pragma unroll
            for (int pr = 0; pr < 2; pr++) {
                uint32_t off = ((b_row + pr * 16) * LDA + akb + b_kh) * 2;
                uint32_t t4[4];
                ldm_x4(t4, b_base + off);
                bh[pr * 2][0] = t4[0]; bh[pr * 2][1] = t4[1];
                bh[pr * 2 + 1][0] = t4[2]; bh[pr * 2 + 1][1] = t4[3];
            }
            #pragma unroll
            for (int tm = 0; tm < 2; tm++)
                #pragma unroll
                for (int tn = 0; tn < 4; tn++)
                    mma_f16(acc[tm][tn], ah[tm], bh[tn]);
        }
        __syncthreads();
    }

    // ---- epilogue: write h (fp16), fused attention halves ----
    int qr = lane >> 2, qc = lane & 3;
    #pragma unroll
    for (int tm = 0; tm < 2; tm++) {
        #pragma unroll
        for (int half = 0; half < 2; half++) {
            int r = wm * 32 + tm * 16 + half * 8 + qr;
            int grow = row0 + r;
            float ps = 0.f, pd = 0.f;
            #pragma unroll
            for (int tn = 0; tn < 4; tn++) {
                float c0 = acc[tm][tn][half * 2];
                float c1 = acc[tm][tn][half * 2 + 1];
                int col = wn * 32 + tn * 8 + qc * 2;
                ps = fmaf(c0, sAs[col], fmaf(c1, sAs[col + 1], ps));
                pd = fmaf(c0, sAd[col], fmaf(c1, sAd[col + 1], pd));
                if (grow < NN)
                    *(__half2*)&g_hh[(size_t)grow * HC + col] = __floats2half2_rn(c0, c1);
            }
            atomicAdd(&sa[r * NH + wn], ps);
            atomicAdd(&sd[r * NH + wn], pd);
        }
    }
    __syncthreads();
    if (tid < 256) {
        int r = tid >> 2, hh = tid & 3;
        int grow = row0 + r;
        if (grow < NN) {
            g_asrc[grow * NH + hh] = sa[r * NH + hh];
            g_adst[grow * NH + hh] = sd[r * NH + hh];
        }
    }
}

// ---------------- single-pass softmax-aggregate (warp per node) -------------
// out = (sum_e p_e * h_src(e)) / (sum_e p_e); p_e = exp(lrelu(logit)).
// Chunk stage computes 32 edges' exps vectorially into per-warp smem;
// inner loop is LDS+LDS+LDG.64+FMA only (no SHFL / MUFU / scalar LDG).
__device__ __forceinline__ float lrelu(float v) { return v > 0.f ? v : 0.2f * v; }

__global__ void __launch_bounds__(256) k_gat(
    const float* __restrict__ bias, float* __restrict__ out)
{
    __shared__ int   sj[8][32];
    __shared__ float sp[8][NH * 33];       // pad 33: head*33+t hits distinct banks

    int wip = threadIdx.x >> 5;
    int w = (blockIdx.x * blockDim.x + threadIdx.x) >> 5;
    int lane = threadIdx.x & 31;
    if (w >= NN) return;

    int o0 = g_off[w];
    int d = g_off[w + 1] - o0;
    int head = lane >> 3;                  // lane owns channels lane*4..lane*4+3
    float4 adst = *(const float4*)&g_adst[w * NH];
    int*   mj = sj[wip];
    float* mp = sp[wip];

    float psum = 0.f;
    float4 acc = make_float4(0.f, 0.f, 0.f, 0.f);
    for (int base = 0; base < d; base += 32) {
        int idx = base + lane;
        if (idx < d) {
            int j = g_srt[o0 + idx];
            float4 as = *(const float4*)&g_asrc[j * NH];
            mj[lane] = j;
            mp[0 * 33 + lane] = __expf(lrelu(as.x + adst.x));
            mp[1 * 33 + lane] = __expf(lrelu(as.y + adst.y));
            mp[2 * 33 + lane] = __expf(lrelu(as.z + adst.z));
            mp[3 * 33 + lane] = __expf(lrelu(as.w + adst.w));
        }
        __syncwarp();
        int cnt = min(32, d - base);
        for (int t = 0; t < cnt; t++) {
            int j = mj[t];                         // broadcast LDS
            float p = mp[head * 33 + t];           // 4 banks, 8-lane broadcast
            psum += p;
            uint2 u = *(const uint2*)&g_hh[(size_t)j * HC + lane * 4];
            float2 f0 = __half22float2(*(__half2*)&u.x);
            float2 f1 = __half22float2(*(__half2*)&u.y);
            acc.x = fmaf(p, f0.x, acc.x);
            acc.y = fmaf(p, f0.y, acc.y);
            acc.z = fmaf(p, f1.x, acc.z);
            acc.w = fmaf(p, f1.y, acc.w);
        }
        __syncwarp();
    }
    float ih = 1.f / (psum + 1e-16f);
    float4 b = *(const float4*)&bias[lane * 4];
    float4 o = make_float4(fmaf(acc.x, ih, b.x), fmaf(acc.y, ih, b.y),
                           fmaf(acc.z, ih, b.z), fmaf(acc.w, ih, b.w));
    *(float4*)&out[(size_t)w * HC + lane * 4] = o;
}

// ---------------- launch ----------------------------------------------------
extern "C" void kernel_launch(void* const* d_in, const int* in_sizes, int n_in,
                              void* d_out, int out_size)
{
    const float* x     = (const float*)d_in[0];
    const int*   ei    = (const int*)d_in[1];
    const float* W     = (const float*)d_in[2];
    const float* att_s = (const float*)d_in[3];
    const float* att_d = (const float*)d_in[4];
    const float* bias  = (const float*)d_in[5];
    float* out = (float*)d_out;

    const int NB = (NN + 1023) / 1024;   // 98

    static cudaStream_t s2 = nullptr;
    static cudaEvent_t evA = nullptr, evB = nullptr;
    if (s2 == nullptr) {
        cudaStreamCreate(&s2);
        cudaEventCreateWithFlags(&evA, cudaEventDisableTiming);
        cudaEventCreateWithFlags(&evB, cudaEventDisableTiming);
    }

    // fork: CSR build on side stream, concurrent with W-prep + GEMM
    cudaEventRecord(evA, 0);
    cudaStreamWaitEvent(s2, evA, 0);

    k_hist<<<(NE + 255) / 256, 256, 0, s2>>>(ei);
    k_scan1<<<NB, 1024, 0, s2>>>();
    k_scan2<<<1, 128, 0, s2>>>();
    k_scan3<<<(NN + 255) / 256, 256, 0, s2>>>();
    k_fill<<<(NET + 255) / 256, 256, 0, s2>>>(ei);
    cudaEventRecord(evB, s2);

    k_prepw<<<(HC * FF + 255) / 256, 256>>>(W);
    k_gemm<<<(NN + 63) / 64, 256>>>(x, att_s, att_d);

    // join: k_gat needs both CSR and GEMM results
    cudaStreamWaitEvent(0, evB, 0);
    k_gat<<<(NN * 32 + 255) / 256, 256>>>(bias, out);
}